// round 11
// baseline (speedup 1.0000x reference)
#include <cuda_runtime.h>
#include <cuda_bf16.h>
#include <math.h>
#include <stdint.h>

// Problem dims
#define BB 4096
#define UU 256
#define DD 128

// Single persistent kernel, grid 128 (<= 148 SMs, 1 CTA/SM guaranteed):
//   P1: convert x/W/bias -> deduped pre-swizzled bf16 images + nv2/cons
//   P2: dual GEMM (K = 3*128 split as 4 physical chunks) + e = 2^logit
//   P3: out = e / rowsum
// Global ticket barrier between phases (monotonic counter, replay-safe).
#define A_MT_U4 4096             // 4 chunks x 1024 uint4 per mtile
#define B_NT_U4 4096
#define SM_A 0                   // 4 x 16KB A chunks
#define SM_B 65536               // 4 x 16KB B chunks
#define SM_SUM 131072            // 128 rows x 4 floats
#define FUSED_SMEM (131072 + 2048)

__device__ float4   g_cons[UU];          // {nb2, bw, sqrt(ww), 0}
__device__ float    g_nv2[BB];
__device__ uint4    g_A[32 * A_MT_U4];   // 2 MB pre-swizzled A (hi0,hi1,lo0,lo1)
__device__ uint4    g_B[4 * B_NT_U4];    // 256 KB pre-swizzled B
__device__ float    g_e[BB * UU];        // 4 MB: e = 2^logit
__device__ float4   g_part[BB];          // per-row partial sums (one per ntile)
__device__ unsigned g_bar[2];            // monotonic barrier counters

// ---------------------------------------------------------------------------
// PTX helpers
// ---------------------------------------------------------------------------
__device__ __forceinline__ uint32_t smem_u32(const void* p) {
    uint32_t a;
    asm("{ .reg .u64 t; cvta.to.shared.u64 t, %1; cvt.u32.u64 %0, t; }"
        : "=r"(a) : "l"(p));
    return a;
}
#define CP16(dst, src) \
    asm volatile("cp.async.cg.shared.global [%0], [%1], 16;" \
                 :: "r"(dst), "l"(src) : "memory")
#define CP_COMMIT() asm volatile("cp.async.commit_group;" ::: "memory")
#define CP_WAITG(n) asm volatile("cp.async.wait_group " #n ";" ::: "memory")
#define LDSM4(r0, r1, r2, r3, addr) \
    asm volatile("ldmatrix.sync.aligned.m8n8.x4.shared.b16 {%0,%1,%2,%3}, [%4];" \
                 : "=r"(r0), "=r"(r1), "=r"(r2), "=r"(r3) : "r"(addr))
#define MMA16816(d0, d1, d2, d3, a0, a1, a2, a3, b0, b1) \
    asm volatile("mma.sync.aligned.m16n8k16.row.col.f32.bf16.bf16.f32 " \
                 "{%0,%1,%2,%3}, {%4,%5,%6,%7}, {%8,%9}, {%0,%1,%2,%3};" \
                 : "+f"(d0), "+f"(d1), "+f"(d2), "+f"(d3) \
                 : "r"(a0), "r"(a1), "r"(a2), "r"(a3), "r"(b0), "r"(b1))

__device__ __forceinline__ float fast_sqrt(float v) {
    float r;
    asm("sqrt.approx.f32 %0, %1;" : "=f"(r) : "f"(v));
    return r;
}

__device__ __forceinline__ void split_bf16(float v, __nv_bfloat16& hi, __nv_bfloat16& lo) {
    hi = __float2bfloat16(v);
    lo = __float2bfloat16(v - __bfloat162float(hi));
}
__device__ __forceinline__ void split8(const float4 a, const float4 b,
                                       uint4& hq, uint4& lq) {
    union { __nv_bfloat16 h[8]; uint4 q; } hi, lo;
    float v[8] = {a.x, a.y, a.z, a.w, b.x, b.y, b.z, b.w};
    #pragma unroll
    for (int i = 0; i < 8; i++) split_bf16(v[i], hi.h[i], lo.h[i]);
    hq = hi.q;
    lq = lo.q;
}

// e = 2^(hyperbolic logit); |logit| = O(5), so max-free softmax is safe
__device__ __forceinline__ float elogit_f(float xw, float xb, float nv2,
                                          float nb2, float bw, float sww) {
    float beta = 1.0f - nb2;
    float bsw  = beta * sww;
    float t2 = -2.0f * xb;
    float alpha = 1.0f + t2 + nv2;
    float dd = 1.0f + t2 + nb2 * nv2;
    float num = 2.0f * beta * (beta * xw - alpha * bw);
    float smm_num = alpha * alpha * nb2 - 2.0f * alpha * beta * xb
                    + beta * beta * nv2;
    float arg = __fdividef(num * dd, (dd * dd - smm_num) * bsw);
    float s = arg + fast_sqrt(fmaf(arg, arg, 1.0f));
    return exp2f((2.0f * sww) * __log2f(s));
}

// grid barrier: ticket-based, monotonic counter (replay-safe), 128 arrivals
__device__ __forceinline__ void gbar(unsigned* ctr) {
    __syncthreads();
    if (threadIdx.x == 0) {
        __threadfence();                       // release all CTA stores
        unsigned t = atomicAdd(ctr, 1u);
        unsigned target = (t / 128u + 1u) * 128u;
        volatile unsigned* vc = ctr;
        while (*vc < target) { }
        __threadfence();                       // acquire
    }
    __syncthreads();
}

// ---------------------------------------------------------------------------
// Fused persistent kernel. grid 128, block 256, smem 130KB+2KB.
// ---------------------------------------------------------------------------
__global__ void __launch_bounds__(256, 1)
fused_kernel(const float* __restrict__ x,
             const float* __restrict__ W,
             const float* __restrict__ bias,
             float* __restrict__ out) {
    extern __shared__ __align__(1024) char smem[];
    __shared__ float red[2][4][3];
    uint32_t sbase = smem_u32(smem);
    const int c   = blockIdx.x;
    const int tid = threadIdx.x;
    const int wid = tid >> 5, lane = tid & 31;

    // ===================== P1-A: rows 32c..32c+31 =====================
    {
        const int rt = tid >> 4;        // 0..15
        const int kg = tid & 15;
        const int half = kg >> 3, k16 = kg & 7;
        const float4* x4 = reinterpret_cast<const float4*>(x)
                         + (c * 32) * 32 + kg * 2;
        #pragma unroll
        for (int rr = 0; rr < 2; rr++) {
            int rloc = rt + rr * 16;    // 0..31
            float4 a = x4[rloc * 32];
            float4 b = x4[rloc * 32 + 1];
            uint4 hq, lq;
            split8(a, b, hq, lq);
            float s = a.x * a.x + a.y * a.y + a.z * a.z + a.w * a.w
                    + b.x * b.x + b.y * b.y + b.z * b.z + b.w * b.w;
            #pragma unroll
            for (int sh = 8; sh > 0; sh >>= 1)
                s += __shfl_xor_sync(0xffffffffu, s, sh);
            int g = c * 32 + rloc;
            if (kg == 0) g_nv2[g] = s;
            int mt = g >> 7, rl = g & 127;
            int off16 = (rl >> 3) * 64 + (rl & 7) * 8 + (k16 ^ (rl & 7));
            uint4* base = g_A + mt * A_MT_U4;
            base[half * 1024 + off16]       = hq;
            base[(2 + half) * 1024 + off16] = lq;
        }
    }

    // ===================== P1-B: u = 2c, 2c+1 =====================
    float* swb = reinterpret_cast<float*>(smem);   // [2][2][128] staging
    {
        int ut = tid >> 7, k = tid & 127;
        int u = 2 * c + ut;
        float w = W[u * DD + k];
        float b = bias[u * DD + k];
        swb[ut * 256 + k]       = w;
        swb[ut * 256 + 128 + k] = b;
        float nb2 = b * b, bw = b * w, ww = w * w;
        #pragma unroll
        for (int sh = 16; sh > 0; sh >>= 1) {
            nb2 += __shfl_xor_sync(0xffffffffu, nb2, sh);
            bw  += __shfl_xor_sync(0xffffffffu, bw,  sh);
            ww  += __shfl_xor_sync(0xffffffffu, ww,  sh);
        }
        if (lane == 0) {
            red[ut][wid & 3][0] = nb2;
            red[ut][wid & 3][1] = bw;
            red[ut][wid & 3][2] = ww;
        }
    }
    __syncthreads();
    if (tid < 2) {
        float n2  = red[tid][0][0] + red[tid][1][0] + red[tid][2][0] + red[tid][3][0];
        float bw_ = red[tid][0][1] + red[tid][1][1] + red[tid][2][1] + red[tid][3][1];
        float ww_ = red[tid][0][2] + red[tid][1][2] + red[tid][2][2] + red[tid][3][2];
        g_cons[2 * c + tid] = make_float4(n2, bw_, sqrtf(ww_), 0.0f);
    }
    if (tid < 64) {
        int ut = tid >> 5, which = (tid >> 4) & 1, kg = tid & 15;
        const float4* s4 = reinterpret_cast<const float4*>(
                               swb + ut * 256 + which * 128);
        float4 a = s4[kg * 2], b = s4[kg * 2 + 1];
        uint4 hq, lq;
        split8(a, b, hq, lq);
        int n = 4 * c + 2 * ut + which;            // paired cols: 2u + which
        int nt = n >> 7, nloc = n & 127;
        int half = kg >> 3, k16 = kg & 7;
        int off16 = (nloc >> 3) * 64 + (nloc & 7) * 8 + (k16 ^ (nloc & 7));
        uint4* base = g_B + nt * B_NT_U4;
        base[half * 1024 + off16]       = hq;
        base[(2 + half) * 1024 + off16] = lq;
    }

    gbar(&g_bar[0]);

    // ===================== P2: GEMM + e-epilogue =====================
    const int ntile = c & 3, mtile = c >> 2;
    {
        const uint4* gAim = g_A + mtile * A_MT_U4;
        const uint4* gBim = g_B + ntile * B_NT_U4;
        #pragma unroll
        for (int ch = 0; ch < 4; ch++) {
            uint32_t dA = sbase + SM_A + ch * 16384;
            uint32_t dB = sbase + SM_B + ch * 16384;
            const uint4* sa = gAim + ch * 1024;
            const uint4* sb = gBim + ch * 1024;
            #pragma unroll
            for (int i = 0; i < 4; i++) CP16(dA + (tid + 256 * i) * 16, sa + tid + 256 * i);
            #pragma unroll
            for (int i = 0; i < 4; i++) CP16(dB + (tid + 256 * i) * 16, sb + tid + 256 * i);
            CP_COMMIT();
        }
    }

    const int m0 = (wid & 1) * 64;
    const int n0 = (wid >> 1) * 32;
    const int rowa  = m0 + (lane & 15);
    const int abase = (rowa >> 3) * 64 + (rowa & 7) * 8;
    const int aswz  = rowa & 7;
    const int akus  = lane >> 4;
    const int rowb  = n0 + (lane & 7) + ((lane >> 4) << 3);
    const int bbase = (rowb >> 3) * 64 + (rowb & 7) * 8;
    const int bswz  = rowb & 7;
    const int bkus  = (lane >> 3) & 1;

    float d[4][4][4];
    #pragma unroll
    for (int i = 0; i < 4; i++)
        #pragma unroll
        for (int j = 0; j < 4; j++)
            #pragma unroll
            for (int q = 0; q < 4; q++) d[i][j][q] = 0.0f;

    // logical chunk -> physical chunk (hi dedup)
    const int pa[6] = {0, 1, 0, 1, 2, 3};
    const int pb[6] = {0, 1, 2, 3, 0, 1};

    #pragma unroll
    for (int l = 0; l < 6; l++) {
        if (l == 0) { CP_WAITG(3); __syncthreads(); }
        else if (l == 1) { CP_WAITG(2); __syncthreads(); }
        else if (l == 2) { CP_WAITG(1); __syncthreads(); }
        else if (l == 3) { CP_WAITG(0); __syncthreads(); }

        uint32_t aB = sbase + SM_A + pa[l] * 16384;
        uint32_t bB = sbase + SM_B + pb[l] * 16384;

        #pragma unroll
        for (int kk = 0; kk < 4; kk++) {
            uint32_t af[4][4];
            #pragma unroll
            for (int mf = 0; mf < 4; mf++) {
                uint32_t addr = aB + ((abase + mf * 128 +
                                       ((2 * kk + akus) ^ aswz)) << 4);
                LDSM4(af[mf][0], af[mf][1], af[mf][2], af[mf][3], addr);
            }
            uint32_t bf[2][4];
            #pragma unroll
            for (int h = 0; h < 2; h++) {
                uint32_t addr = bB + ((bbase + h * 128 +
                                       ((2 * kk + bkus) ^ bswz)) << 4);
                LDSM4(bf[h][0], bf[h][1], bf[h][2], bf[h][3], addr);
            }
            #pragma unroll
            for (int mf = 0; mf < 4; mf++)
                #pragma unroll
                for (int nf = 0; nf < 4; nf++)
                    MMA16816(d[mf][nf][0], d[mf][nf][1], d[mf][nf][2], d[mf][nf][3],
                             af[mf][0], af[mf][1], af[mf][2], af[mf][3],
                             bf[nf >> 1][(nf & 1) * 2], bf[nf >> 1][(nf & 1) * 2 + 1]);
        }
    }

    // fused epilogue: e = 2^logit + per-row quad partial sums
    {
        float* ssum = reinterpret_cast<float*>(smem + SM_SUM);   // [128][4]
        const int rloc0 = m0 + (lane >> 2);
        const int rbase = mtile * 128 + rloc0;
        const int ubase = ntile * 64 + (wid >> 1) * 16 + (lane & 3);

        float4 cons[4];
        #pragma unroll
        for (int nf = 0; nf < 4; nf++)
            cons[nf] = __ldcg(&g_cons[ubase + nf * 4]);
        float nv2a[4], nv2b[4];
        #pragma unroll
        for (int mf = 0; mf < 4; mf++) {
            nv2a[mf] = __ldcg(&g_nv2[rbase + mf * 16]);
            nv2b[mf] = __ldcg(&g_nv2[rbase + mf * 16 + 8]);
        }

        float sa[4], sb2[4];
        #pragma unroll
        for (int mf = 0; mf < 4; mf++) { sa[mf] = 0.0f; sb2[mf] = 0.0f; }

        #pragma unroll
        for (int mf = 0; mf < 4; mf++)
            #pragma unroll
            for (int nf = 0; nf < 4; nf++) {
                int u = ubase + nf * 4;
                float4 cs = cons[nf];
                float ea = elogit_f(d[mf][nf][0], d[mf][nf][1], nv2a[mf],
                                    cs.x, cs.y, cs.z);
                float eb = elogit_f(d[mf][nf][2], d[mf][nf][3], nv2b[mf],
                                    cs.x, cs.y, cs.z);
                g_e[(rbase + mf * 16) * UU + u] = ea;
                g_e[(rbase + mf * 16 + 8) * UU + u] = eb;
                sa[mf] += ea;
                sb2[mf] += eb;
            }

        #pragma unroll
        for (int mf = 0; mf < 4; mf++) {
            sa[mf]  += __shfl_xor_sync(0xffffffffu, sa[mf],  1);
            sa[mf]  += __shfl_xor_sync(0xffffffffu, sa[mf],  2);
            sb2[mf] += __shfl_xor_sync(0xffffffffu, sb2[mf], 1);
            sb2[mf] += __shfl_xor_sync(0xffffffffu, sb2[mf], 2);
        }
        const int wn = wid >> 1;
        if ((lane & 3) == 0) {
            #pragma unroll
            for (int mf = 0; mf < 4; mf++) {
                int rl = m0 + mf * 16 + (lane >> 2);
                ssum[rl * 4 + wn] = sa[mf];
                ssum[(rl + 8) * 4 + wn] = sb2[mf];
            }
        }
        __syncthreads();
        if (tid < 128) {
            float4 v = reinterpret_cast<float4*>(ssum)[tid];
            float* p = reinterpret_cast<float*>(&g_part[mtile * 128 + tid]);
            p[ntile] = v.x + v.y + v.z + v.w;
        }
    }

    gbar(&g_bar[1]);

    // ===================== P3: scale rows 32c..32c+31 =====================
    {
        const int row = c * 32 + (tid >> 3);
        const int j0  = tid & 7;
        float4 p = __ldcg(&g_part[row]);
        float inv = __fdividef(1.0f, p.x + p.y + p.z + p.w);
        const float4* e4 = reinterpret_cast<const float4*>(g_e) + row * 64;
        float4* o4 = reinterpret_cast<float4*>(out) + row * 64;
        #pragma unroll
        for (int j = 0; j < 8; j++) {
            float4 v = __ldcg(&e4[j * 8 + j0]);
            v.x *= inv; v.y *= inv; v.z *= inv; v.w *= inv;
            o4[j * 8 + j0] = v;
        }
    }
}

// ---------------------------------------------------------------------------
extern "C" void kernel_launch(void* const* d_in, const int* in_sizes, int n_in,
                              void* d_out, int out_size) {
    const float* x    = (const float*)d_in[0];
    const float* W    = (const float*)d_in[1];
    const float* bias = (const float*)d_in[2];
    float* out = (float*)d_out;

    cudaFuncSetAttribute(fused_kernel,
                         cudaFuncAttributeMaxDynamicSharedMemorySize, FUSED_SMEM);

    fused_kernel<<<128, 256, FUSED_SMEM>>>(x, W, bias, out);
}

// round 12
// speedup vs baseline: 1.1026x; 1.1026x over previous
#include <cuda_runtime.h>
#include <cuda_bf16.h>
#include <math.h>
#include <stdint.h>

// Problem dims
#define BB 4096
#define UU 256
#define DD 128

// GEMM: C[4096, 512] = A[4096, 384]bf16 . B[512, 384]bf16^T, fp32 accum
// K = 3*128 (hi*hi, hi*lo, lo*hi), hi chunks DEDUPED: images hold 4 physical
// chunks (hi0, hi1, lo0, lo1); logical->physical: pa={0,1,0,1,2,3},
// pb={0,1,2,3,0,1}. B columns PAIR-interleaved (col 2u = W_u, col 2u+1 =
// bias_u) so each MMA (d0,d1) = (xw, xb). Epilogue: e = 2^logit + partials.
#define A_MT_U4 4096             // 4 chunks x 1024 uint4 per 128-row mtile
#define B_NT_U4 4096
#define SM_A 0                   // 4 x 16KB A chunks
#define SM_B 65536               // 4 x 16KB B chunks
#define SM_SUM 131072            // 128 rows x 4 floats
#define GEMM_SMEM (131072 + 2048)

__device__ float4 g_cons[UU];            // {nb2, bw, sqrt(ww), 0}
__device__ float  g_nv2[BB];
__device__ uint4  g_A[32 * A_MT_U4];     // 2 MB pre-swizzled A
__device__ uint4  g_B[4 * B_NT_U4];      // 256 KB pre-swizzled B
__device__ float  g_e[BB * UU];          // 4 MB: e = 2^logit
__device__ float4 g_part[BB];            // per-row partial sums (per ntile)

// ---------------------------------------------------------------------------
// PTX helpers
// ---------------------------------------------------------------------------
__device__ __forceinline__ uint32_t smem_u32(const void* p) {
    uint32_t a;
    asm("{ .reg .u64 t; cvta.to.shared.u64 t, %1; cvt.u32.u64 %0, t; }"
        : "=r"(a) : "l"(p));
    return a;
}
#define CP16(dst, src) \
    asm volatile("cp.async.cg.shared.global [%0], [%1], 16;" \
                 :: "r"(dst), "l"(src) : "memory")
#define CP_COMMIT() asm volatile("cp.async.commit_group;" ::: "memory")
#define CP_WAITG(n) asm volatile("cp.async.wait_group " #n ";" ::: "memory")
#define LDSM4(r0, r1, r2, r3, addr) \
    asm volatile("ldmatrix.sync.aligned.m8n8.x4.shared.b16 {%0,%1,%2,%3}, [%4];" \
                 : "=r"(r0), "=r"(r1), "=r"(r2), "=r"(r3) : "r"(addr))
#define MMA16816(d0, d1, d2, d3, a0, a1, a2, a3, b0, b1) \
    asm volatile("mma.sync.aligned.m16n8k16.row.col.f32.bf16.bf16.f32 " \
                 "{%0,%1,%2,%3}, {%4,%5,%6,%7}, {%8,%9}, {%0,%1,%2,%3};" \
                 : "+f"(d0), "+f"(d1), "+f"(d2), "+f"(d3) \
                 : "r"(a0), "r"(a1), "r"(a2), "r"(a3), "r"(b0), "r"(b1))

__device__ __forceinline__ float fast_sqrt(float v) {
    float r;
    asm("sqrt.approx.f32 %0, %1;" : "=f"(r) : "f"(v));
    return r;
}

__device__ __forceinline__ void split_bf16(float v, __nv_bfloat16& hi, __nv_bfloat16& lo) {
    hi = __float2bfloat16(v);
    lo = __float2bfloat16(v - __bfloat162float(hi));
}
__device__ __forceinline__ void split8(const float4 a, const float4 b,
                                       uint4& hq, uint4& lq) {
    union { __nv_bfloat16 h[8]; uint4 q; } hi, lo;
    float v[8] = {a.x, a.y, a.z, a.w, b.x, b.y, b.z, b.w};
    #pragma unroll
    for (int i = 0; i < 8; i++) split_bf16(v[i], hi.h[i], lo.h[i]);
    hq = hi.q;
    lq = lo.q;
}
__device__ __forceinline__ float dot8(const float4 a, const float4 b) {
    return a.x * a.x + a.y * a.y + a.z * a.z + a.w * a.w
         + b.x * b.x + b.y * b.y + b.z * b.z + b.w * b.w;
}

// e = 2^(hyperbolic logit); |logit| = O(5), so max-free softmax is safe
__device__ __forceinline__ float elogit_f(float xw, float xb, float nv2,
                                          float nb2, float bw, float sww) {
    float beta = 1.0f - nb2;
    float bsw  = beta * sww;
    float t2 = -2.0f * xb;
    float alpha = 1.0f + t2 + nv2;
    float dd = 1.0f + t2 + nb2 * nv2;
    float num = 2.0f * beta * (beta * xw - alpha * bw);
    float smm_num = alpha * alpha * nb2 - 2.0f * alpha * beta * xb
                    + beta * beta * nv2;
    float arg = __fdividef(num * dd, (dd * dd - smm_num) * bsw);
    float s = arg + fast_sqrt(fmaf(arg, arg, 1.0f));
    return exp2f((2.0f * sww) * __log2f(s));
}

// ---------------------------------------------------------------------------
// Prep: single wave (grid 144). Blocks 0-127: A (2 row-tasks per thread,
// MLP=4). Blocks 128-143: W/bias (1 task, W+bias loaded together, MLP=4).
// ---------------------------------------------------------------------------
__global__ void __launch_bounds__(256)
prep_kernel(const float* __restrict__ x,
            const float* __restrict__ W,
            const float* __restrict__ bias) {
    const int tid = threadIdx.x;
    if (blockIdx.x < 128) {
        const int t = blockIdx.x * 256 + tid;    // task 0..32767
        const int row0 = t >> 4;
        const int row1 = row0 + 2048;
        const int kg = t & 15;
        const int half = kg >> 3, k16 = kg & 7;
        const float4* x4 = reinterpret_cast<const float4*>(x);

        // front-load 4 independent LDG.128
        float4 a0 = x4[row0 * 32 + kg * 2];
        float4 b0 = x4[row0 * 32 + kg * 2 + 1];
        float4 a1 = x4[row1 * 32 + kg * 2];
        float4 b1 = x4[row1 * 32 + kg * 2 + 1];

        uint4 hq0, lq0, hq1, lq1;
        split8(a0, b0, hq0, lq0);
        split8(a1, b1, hq1, lq1);
        float s0 = dot8(a0, b0);
        float s1 = dot8(a1, b1);
        #pragma unroll
        for (int sh = 8; sh > 0; sh >>= 1) {
            s0 += __shfl_xor_sync(0xffffffffu, s0, sh);
            s1 += __shfl_xor_sync(0xffffffffu, s1, sh);
        }
        if (kg == 0) { g_nv2[row0] = s0; g_nv2[row1] = s1; }

        {
            int mt = row0 >> 7, rl = row0 & 127;
            int off16 = (rl >> 3) * 64 + (rl & 7) * 8 + (k16 ^ (rl & 7));
            uint4* base = g_A + mt * A_MT_U4;
            base[half * 1024 + off16]       = hq0;
            base[(2 + half) * 1024 + off16] = lq0;
        }
        {
            int mt = row1 >> 7, rl = row1 & 127;
            int off16 = (rl >> 3) * 64 + (rl & 7) * 8 + (k16 ^ (rl & 7));
            uint4* base = g_A + mt * A_MT_U4;
            base[half * 1024 + off16]       = hq1;
            base[(2 + half) * 1024 + off16] = lq1;
        }
    } else {
        const int t = (blockIdx.x - 128) * 256 + tid;   // 0..4095
        const int u = t >> 4;
        const int kg = t & 15;
        const int half = kg >> 3, k16 = kg & 7;
        const float4* W4 = reinterpret_cast<const float4*>(W);
        const float4* B4 = reinterpret_cast<const float4*>(bias);

        float4 wa = W4[u * 32 + kg * 2];
        float4 wb = W4[u * 32 + kg * 2 + 1];
        float4 ba = B4[u * 32 + kg * 2];
        float4 bb = B4[u * 32 + kg * 2 + 1];

        float nb2 = dot8(ba, bb);
        float ww  = dot8(wa, wb);
        float bw  = ba.x * wa.x + ba.y * wa.y + ba.z * wa.z + ba.w * wa.w
                  + bb.x * wb.x + bb.y * wb.y + bb.z * wb.z + bb.w * wb.w;
        #pragma unroll
        for (int sh = 8; sh > 0; sh >>= 1) {
            nb2 += __shfl_xor_sync(0xffffffffu, nb2, sh);
            bw  += __shfl_xor_sync(0xffffffffu, bw,  sh);
            ww  += __shfl_xor_sync(0xffffffffu, ww,  sh);
        }
        if (kg == 0) g_cons[u] = make_float4(nb2, bw, sqrtf(ww), 0.0f);

        uint4 whq, wlq, bhq, blq;
        split8(wa, wb, whq, wlq);
        split8(ba, bb, bhq, blq);
        {
            int n = 2 * u;                       // W -> even col
            int nt = n >> 7, nloc = n & 127;
            int off16 = (nloc >> 3) * 64 + (nloc & 7) * 8 + (k16 ^ (nloc & 7));
            uint4* base = g_B + nt * B_NT_U4;
            base[half * 1024 + off16]       = whq;
            base[(2 + half) * 1024 + off16] = wlq;
        }
        {
            int n = 2 * u + 1;                   // bias -> odd col
            int nt = n >> 7, nloc = n & 127;
            int off16 = (nloc >> 3) * 64 + (nloc & 7) * 8 + (k16 ^ (nloc & 7));
            uint4* base = g_B + nt * B_NT_U4;
            base[half * 1024 + off16]       = bhq;
            base[(2 + half) * 1024 + off16] = blq;
        }
    }
}

// ---------------------------------------------------------------------------
// GEMM + fused epilogue (e = 2^logit) + per-row partial sums.
// grid (4, 32), block 256 (8 warps). CTA 128 rows x 64 u. Deduped chunks.
// ---------------------------------------------------------------------------
__global__ void __launch_bounds__(256)
gemm_kernel() {
    extern __shared__ __align__(1024) char smem[];
    uint32_t sbase = smem_u32(smem);
    float* ssum = reinterpret_cast<float*>(smem + SM_SUM);   // [128][4]
    const int tid = threadIdx.x;
    const int wid = tid >> 5, lane = tid & 31;
    const int ntile = blockIdx.x, mtile = blockIdx.y;

    const uint4* gAim = g_A + mtile * A_MT_U4;
    const uint4* gBim = g_B + ntile * B_NT_U4;
    #pragma unroll
    for (int ch = 0; ch < 4; ch++) {
        uint32_t dA = sbase + SM_A + ch * 16384;
        uint32_t dB = sbase + SM_B + ch * 16384;
        const uint4* sa = gAim + ch * 1024;
        const uint4* sb = gBim + ch * 1024;
        #pragma unroll
        for (int i = 0; i < 4; i++) CP16(dA + (tid + 256 * i) * 16, sa + tid + 256 * i);
        #pragma unroll
        for (int i = 0; i < 4; i++) CP16(dB + (tid + 256 * i) * 16, sb + tid + 256 * i);
        CP_COMMIT();
    }

    const int m0 = (wid & 1) * 64;
    const int n0 = (wid >> 1) * 32;
    const int rowa  = m0 + (lane & 15);
    const int abase = (rowa >> 3) * 64 + (rowa & 7) * 8;
    const int aswz  = rowa & 7;
    const int akus  = lane >> 4;
    const int rowb  = n0 + (lane & 7) + ((lane >> 4) << 3);
    const int bbase = (rowb >> 3) * 64 + (rowb & 7) * 8;
    const int bswz  = rowb & 7;
    const int bkus  = (lane >> 3) & 1;

    float d[4][4][4];
    #pragma unroll
    for (int i = 0; i < 4; i++)
        #pragma unroll
        for (int j = 0; j < 4; j++)
            #pragma unroll
            for (int q = 0; q < 4; q++) d[i][j][q] = 0.0f;

    // logical chunk -> physical chunk (hi dedup)
    const int pa[6] = {0, 1, 0, 1, 2, 3};
    const int pb[6] = {0, 1, 2, 3, 0, 1};

    #pragma unroll
    for (int l = 0; l < 6; l++) {
        if (l == 0)      { CP_WAITG(3); __syncthreads(); }
        else if (l == 1) { CP_WAITG(2); __syncthreads(); }
        else if (l == 2) { CP_WAITG(1); __syncthreads(); }
        else if (l == 3) { CP_WAITG(0); __syncthreads(); }

        uint32_t aB = sbase + SM_A + pa[l] * 16384;
        uint32_t bB = sbase + SM_B + pb[l] * 16384;

        #pragma unroll
        for (int kk = 0; kk < 4; kk++) {
            uint32_t af[4][4];
            #pragma unroll
            for (int mf = 0; mf < 4; mf++) {
                uint32_t addr = aB + ((abase + mf * 128 +
                                       ((2 * kk + akus) ^ aswz)) << 4);
                LDSM4(af[mf][0], af[mf][1], af[mf][2], af[mf][3], addr);
            }
            uint32_t bf[2][4];
            #pragma unroll
            for (int h = 0; h < 2; h++) {
                uint32_t addr = bB + ((bbase + h * 128 +
                                       ((2 * kk + bkus) ^ bswz)) << 4);
                LDSM4(bf[h][0], bf[h][1], bf[h][2], bf[h][3], addr);
            }
            #pragma unroll
            for (int mf = 0; mf < 4; mf++)
                #pragma unroll
                for (int nf = 0; nf < 4; nf++)
                    MMA16816(d[mf][nf][0], d[mf][nf][1], d[mf][nf][2], d[mf][nf][3],
                             af[mf][0], af[mf][1], af[mf][2], af[mf][3],
                             bf[nf >> 1][(nf & 1) * 2], bf[nf >> 1][(nf & 1) * 2 + 1]);
        }
    }

    // fused epilogue: e = 2^logit + per-row quad partial sums
    const int rloc0 = m0 + (lane >> 2);
    const int rbase = mtile * 128 + rloc0;
    const int ubase = ntile * 64 + (wid >> 1) * 16 + (lane & 3);

    float4 cons[4];
    #pragma unroll
    for (int nf = 0; nf < 4; nf++)
        cons[nf] = g_cons[ubase + nf * 4];
    float nv2a[4], nv2b[4];
    #pragma unroll
    for (int mf = 0; mf < 4; mf++) {
        nv2a[mf] = g_nv2[rbase + mf * 16];
        nv2b[mf] = g_nv2[rbase + mf * 16 + 8];
    }

    float sa[4], sb2[4];
    #pragma unroll
    for (int mf = 0; mf < 4; mf++) { sa[mf] = 0.0f; sb2[mf] = 0.0f; }

    #pragma unroll
    for (int mf = 0; mf < 4; mf++)
        #pragma unroll
        for (int nf = 0; nf < 4; nf++) {
            int u = ubase + nf * 4;
            float4 cs = cons[nf];
            float ea = elogit_f(d[mf][nf][0], d[mf][nf][1], nv2a[mf],
                                cs.x, cs.y, cs.z);
            float eb = elogit_f(d[mf][nf][2], d[mf][nf][3], nv2b[mf],
                                cs.x, cs.y, cs.z);
            g_e[(rbase + mf * 16) * UU + u] = ea;
            g_e[(rbase + mf * 16 + 8) * UU + u] = eb;
            sa[mf] += ea;
            sb2[mf] += eb;
        }

    #pragma unroll
    for (int mf = 0; mf < 4; mf++) {
        sa[mf]  += __shfl_xor_sync(0xffffffffu, sa[mf],  1);
        sa[mf]  += __shfl_xor_sync(0xffffffffu, sa[mf],  2);
        sb2[mf] += __shfl_xor_sync(0xffffffffu, sb2[mf], 1);
        sb2[mf] += __shfl_xor_sync(0xffffffffu, sb2[mf], 2);
    }
    const int wn = wid >> 1;
    if ((lane & 3) == 0) {
        #pragma unroll
        for (int mf = 0; mf < 4; mf++) {
            int rl = m0 + mf * 16 + (lane >> 2);
            ssum[rl * 4 + wn] = sa[mf];
            ssum[(rl + 8) * 4 + wn] = sb2[mf];
        }
    }
    __syncthreads();
    if (tid < 128) {
        float4 v = reinterpret_cast<float4*>(ssum)[tid];
        float* p = reinterpret_cast<float*>(&g_part[mtile * 128 + tid]);
        p[ntile] = v.x + v.y + v.z + v.w;
    }
}

// ---------------------------------------------------------------------------
// Scale: out = e / rowsum. Pure elementwise. grid 2048, block 256 (2 rows).
// ---------------------------------------------------------------------------
__global__ void __launch_bounds__(256)
scale_kernel(float* __restrict__ out) {
    const int tid = threadIdx.x;
    const int row = blockIdx.x * 2 + (tid >> 7);
    const int c2  = tid & 127;     // float2 index within row

    float4 p = g_part[row];
    float inv = __fdividef(1.0f, p.x + p.y + p.z + p.w);
    const float2* e2 = reinterpret_cast<const float2*>(g_e) + row * 128;
    float2 v = e2[c2];
    v.x *= inv;
    v.y *= inv;
    reinterpret_cast<float2*>(out)[row * 128 + c2] = v;
}

// ---------------------------------------------------------------------------
extern "C" void kernel_launch(void* const* d_in, const int* in_sizes, int n_in,
                              void* d_out, int out_size) {
    const float* x    = (const float*)d_in[0];
    const float* W    = (const float*)d_in[1];
    const float* bias = (const float*)d_in[2];
    float* out = (float*)d_out;

    cudaFuncSetAttribute(gemm_kernel,
                         cudaFuncAttributeMaxDynamicSharedMemorySize, GEMM_SMEM);

    prep_kernel<<<144, 256>>>(x, W, bias);
    gemm_kernel<<<dim3(4, 32), 256, GEMM_SMEM>>>();
    scale_kernel<<<BB / 2, 256>>>(out);
}